// round 14
// baseline (speedup 1.0000x reference)
#include <cuda_runtime.h>
#include <math.h>

#define NCOLS   16384
#define NSEG    4
#define SEGLEN  (NCOLS / NSEG)      // 4096
#define SLOTS   832                 // per-segment candidate slots (8σ margin)
#define CAP     (NSEG * SLOTS)      // 3328
#define FTZ     0.5f                // fixed pre-threshold (z units)
#define KSEL    256
#define NT      256
#define NW      (NT / 32)
#define MAXROWS 2048

// global scratch (module-static; no runtime allocation)
__device__ float          g_cval[(size_t)MAXROWS * NSEG * SLOTS];
__device__ unsigned short g_cidx[(size_t)MAXROWS * NSEG * SLOTS];
__device__ float          g_smax[(size_t)MAXROWS * NSEG];
__device__ int            g_scnt[(size_t)MAXROWS * NSEG];

// ---- warp-0 tau solve over a buffer; returns tau/th/useGe/inv and selected count ----
__device__ __forceinline__ void solve_tau(const float* __restrict__ cb, int n,
                                          float scale, float cutoff, float zmax,
                                          int lane, float& tau_o, float& th_o,
                                          float& inv_o, int& useGe_o, int& sel_o)
{
    float tau = cutoff, gfin = 0.f;
    for (int it = 0; it < 24; ++it) {
        float g = 0.f, gp = 0.f;
        for (int i = lane; i < n; i += 32) {
            float d = scale * cb[i] - tau;
            if (d > 0.f) { g = fmaf(d, d, g); gp += d; }
        }
        #pragma unroll
        for (int o = 16; o; o >>= 1) {
            g  += __shfl_xor_sync(0xffffffffu, g,  o);
            gp += __shfl_xor_sync(0xffffffffu, gp, o);
        }
        gfin = g;
        g -= 1.0f;
        if (gp <= 0.f) break;
        float step = g / (2.0f * gp);
        tau += step;
        if (step < 1e-7f) break;
    }
    int S = 0;
    for (int i = lane; i < n; i += 32) S += (scale * cb[i] > tau) ? 1 : 0;
    #pragma unroll
    for (int o = 16; o; o >>= 1) S += __shfl_xor_sync(0xffffffffu, S, o);

    float th = tau;
    int useGe = 0;
    float ssum = gfin;
    if (S > KSEL) {                         // rare: bisect K-th largest z
        useGe = 1;
        float lo = tau, hi = zmax;
        for (int it = 0; it < 48; ++it) {
            float mid = 0.5f * (lo + hi);
            int c = 0;
            for (int i = lane; i < n; i += 32) c += (scale * cb[i] >= mid) ? 1 : 0;
            #pragma unroll
            for (int o = 16; o; o >>= 1) c += __shfl_xor_sync(0xffffffffu, c, o);
            if (c >= KSEL) lo = mid; else hi = mid;
        }
        th = lo;
        ssum = 0.f;
        for (int i = lane; i < n; i += 32) {
            float z = scale * cb[i], d = z - tau;
            if (z >= th && d > 0.f) ssum = fmaf(d, d, ssum);
        }
        #pragma unroll
        for (int o = 16; o; o >>= 1) ssum += __shfl_xor_sync(0xffffffffu, ssum, o);
    }
    float inv = 1.0f / (ssum + 1e-8f);
    int sel = 0;
    for (int i = lane; i < n; i += 32) {
        float z = scale * cb[i], d = z - tau;
        bool keep = useGe ? (z >= th && d > 0.f) : (d > 0.f);
        float w = keep ? d * d * inv : 0.f;
        sel += (w > 1e-6f);
    }
    #pragma unroll
    for (int o = 16; o; o >>= 1) sel += __shfl_xor_sync(0xffffffffu, sel, o);
    tau_o = tau; th_o = th; inv_o = inv; useGe_o = useGe; sel_o = sel;
}

// ================= K1: segment collect (pure stream, 8192 tiny CTAs) =================
__global__ __launch_bounds__(NT, 8)
void k_collect(const float* __restrict__ logits)
{
    __shared__ float s_f[NW];
    __shared__ int   s_i[NW];

    const int seg  = blockIdx.x;
    const int row  = blockIdx.y;
    if (row >= MAXROWS) return;            // handled by K2 fallback
    const int tid  = threadIdx.x;
    const int lane = tid & 31;
    const int wid  = tid >> 5;

    const float4* src = reinterpret_cast<const float4*>(logits)
                      + ((size_t)row * NCOLS + (size_t)seg * SEGLEN) / 4;

    // one streaming sweep: z = 0.5*x, max + count(z > FTZ)
    float4 v[SEGLEN / 4 / NT];             // 4 float4
    float lmax = -INFINITY;
    int   lc = 0;
    #pragma unroll
    for (int j = 0; j < SEGLEN / 4 / NT; ++j) {
        float4 t = __ldcs(&src[tid + j * NT]);
        t.x *= 0.5f; t.y *= 0.5f; t.z *= 0.5f; t.w *= 0.5f;
        v[j] = t;
        lmax = fmaxf(lmax, fmaxf(fmaxf(t.x, t.y), fmaxf(t.z, t.w)));
        lc += (t.x > FTZ) + (t.y > FTZ) + (t.z > FTZ) + (t.w > FTZ);
    }
    float wm = lmax;
    #pragma unroll
    for (int o = 16; o; o >>= 1) wm = fmaxf(wm, __shfl_xor_sync(0xffffffffu, wm, o));
    int inc = lc;
    #pragma unroll
    for (int o = 1; o < 32; o <<= 1) {
        int t = __shfl_up_sync(0xffffffffu, inc, o);
        if (lane >= o) inc += t;
    }
    if (lane == 0)  s_f[wid] = wm;
    if (lane == 31) s_i[wid] = inc;
    __syncthreads();
    float segmax; int segcnt, wbase;
    {
        float m = (lane < NW) ? s_f[lane] : -INFINITY;
        #pragma unroll
        for (int o = 4; o; o >>= 1) m = fmaxf(m, __shfl_xor_sync(0xffffffffu, m, o));
        segmax = __shfl_sync(0xffffffffu, m, 0);
        int a = (lane < NW) ? s_i[lane] : 0;
        int sc = a;
        #pragma unroll
        for (int o = 1; o < NW; o <<= 1) {
            int u = __shfl_up_sync(0xffffffffu, sc, o);
            if (lane >= o) sc += u;
        }
        segcnt = __shfl_sync(0xffffffffu, sc, NW - 1);
        wbase  = __shfl_sync(0xffffffffu, sc - a, wid);
    }

    // compact (value, in-segment index) to fixed slots; deterministic layout
    const size_t sb = ((size_t)row * NSEG + seg) * SLOTS;
    int o = wbase + (inc - lc);
    #pragma unroll
    for (int j = 0; j < SEGLEN / 4 / NT; ++j) {
        const int base = 4 * (tid + j * NT);
        float z;
        z = v[j].x; if (z > FTZ) { if (o < SLOTS) { g_cval[sb+o] = z; g_cidx[sb+o] = (unsigned short)(base);   } ++o; }
        z = v[j].y; if (z > FTZ) { if (o < SLOTS) { g_cval[sb+o] = z; g_cidx[sb+o] = (unsigned short)(base+1); } ++o; }
        z = v[j].z; if (z > FTZ) { if (o < SLOTS) { g_cval[sb+o] = z; g_cidx[sb+o] = (unsigned short)(base+2); } ++o; }
        z = v[j].w; if (z > FTZ) { if (o < SLOTS) { g_cval[sb+o] = z; g_cidx[sb+o] = (unsigned short)(base+3); } ++o; }
    }
    if (tid == 0) {
        g_smax[(size_t)row * NSEG + seg] = segmax;
        g_scnt[(size_t)row * NSEG + seg] = segcnt;
    }
}

// ================= K2: zero-fill + gather + solve + scatter (1 CTA/row) =================
__global__ __launch_bounds__(NT)
void k_finish(const float* __restrict__ logits,
              float* __restrict__ out_w, float* __restrict__ out_cnt)
{
    __shared__ float          cand[CAP];
    __shared__ unsigned short sidx[CAP];
    __shared__ float s_f[NW];
    __shared__ int   s_i[NW];
    __shared__ float s_tau, s_th, s_inv;
    __shared__ int   s_useGe;

    const int row  = blockIdx.x;
    const int tid  = threadIdx.x;
    const int lane = tid & 31;
    const int wid  = tid >> 5;

    float4* dst = reinterpret_cast<float4*>(out_w) + (size_t)row * (NCOLS / 4);

    // read per-segment stats
    bool fb = (row >= MAXROWS);
    float zmax = -INFINITY;
    int cnt[NSEG], pref[NSEG], cn = 0;
    if (!fb) {
        const size_t rb = (size_t)row * NSEG;
        #pragma unroll
        for (int s = 0; s < NSEG; ++s) {
            zmax = fmaxf(zmax, g_smax[rb + s]);
            int c = g_scnt[rb + s];
            cnt[s] = c; pref[s] = cn; cn += c;
            fb = fb || (c > SLOTS);
        }
        fb = fb || (zmax - 1.0f < FTZ) || (cn > CAP);
    }

    if (!fb) {
        const float cutoff = zmax - 1.0f;
        // zero-fill output row immediately (write-only stream; drains during solve)
        const float4 zer = make_float4(0.f, 0.f, 0.f, 0.f);
        #pragma unroll 4
        for (int j = 0; j < NCOLS / 4 / NT; ++j) __stcs(&dst[tid + j * NT], zer);

        // gather superset candidates into smem (deterministic segment-major order)
        const size_t rb = (size_t)row * NSEG;
        #pragma unroll
        for (int s = 0; s < NSEG; ++s) {
            const size_t sb = (rb + s) * SLOTS;
            for (int i = tid; i < cnt[s]; i += NT) {
                cand[pref[s] + i] = g_cval[sb + i];
                sidx[pref[s] + i] = (unsigned short)(s * SEGLEN + g_cidx[sb + i]);
            }
        }
        __syncthreads();

        if (wid == 0) {
            float tau, th, inv; int useGe, sel;
            solve_tau(cand, cn, 1.0f, cutoff, zmax, lane, tau, th, inv, useGe, sel);
            if (lane == 0) {
                s_tau = tau; s_th = th; s_useGe = useGe; s_inv = inv;
                out_cnt[row] = (float)sel;
            }
        }
        __syncthreads();

        const float tau = s_tau, th = s_th, inv = s_inv;
        const bool  useGe = (s_useGe != 0);
        float* orow = out_w + (size_t)row * NCOLS;
        for (int i = tid; i < cn; i += NT) {
            float z = cand[i], d = z - tau;
            bool keep = useGe ? (z >= th && d > 0.f) : (d > 0.f);
            if (keep) orow[sidx[i]] = d * d * inv;
        }
        return;
    }

    // ---------- exact full-row fallback (astronomically rare / row >= MAXROWS) ----------
    const float4* src = reinterpret_cast<const float4*>(logits) + (size_t)row * (NCOLS / 4);
    float lmax = -INFINITY;
    #pragma unroll 4
    for (int j = 0; j < NCOLS / 4 / NT; ++j) {
        float4 t = src[tid + j * NT];
        lmax = fmaxf(lmax, fmaxf(fmaxf(t.x, t.y), fmaxf(t.z, t.w)));
    }
    #pragma unroll
    for (int o = 16; o; o >>= 1) lmax = fmaxf(lmax, __shfl_xor_sync(0xffffffffu, lmax, o));
    if (lane == 0) s_f[wid] = lmax;
    __syncthreads();
    {
        float m = (lane < NW) ? s_f[lane] : -INFINITY;
        #pragma unroll
        for (int o = 4; o; o >>= 1) m = fmaxf(m, __shfl_xor_sync(0xffffffffu, m, o));
        lmax = __shfl_sync(0xffffffffu, m, 0);
    }
    const float zm = 0.5f * lmax;
    if (wid == 0) {
        float tau, th, inv; int useGe, sel;
        solve_tau(logits + (size_t)row * NCOLS, NCOLS, 0.5f, zm - 1.0f, zm, lane,
                  tau, th, inv, useGe, sel);
        if (lane == 0) {
            s_tau = tau; s_th = th; s_useGe = useGe; s_inv = inv;
            out_cnt[row] = (float)sel;
        }
    }
    __syncthreads();
    const float tau = s_tau, th = s_th, inv = s_inv;
    const bool  useGe = (s_useGe != 0);
    #pragma unroll 4
    for (int j = 0; j < NCOLS / 4 / NT; ++j) {
        float4 t = src[tid + j * NT];
        float4 w;
        { float z = 0.5f*t.x, d = z-tau; bool k = useGe ? (z>=th && d>0.f):(d>0.f); w.x = k ? d*d*inv : 0.f; }
        { float z = 0.5f*t.y, d = z-tau; bool k = useGe ? (z>=th && d>0.f):(d>0.f); w.y = k ? d*d*inv : 0.f; }
        { float z = 0.5f*t.z, d = z-tau; bool k = useGe ? (z>=th && d>0.f):(d>0.f); w.z = k ? d*d*inv : 0.f; }
        { float z = 0.5f*t.w, d = z-tau; bool k = useGe ? (z>=th && d>0.f):(d>0.f); w.w = k ? d*d*inv : 0.f; }
        __stcs(&dst[tid + j * NT], w);
    }
}

extern "C" void kernel_launch(void* const* d_in, const int* in_sizes, int n_in,
                              void* d_out, int out_size)
{
    const float* logits = (const float*)d_in[0];
    float* out = (float*)d_out;
    const int B = in_sizes[0] / NCOLS;

    dim3 g1(NSEG, B);
    k_collect<<<g1, NT>>>(logits);
    k_finish<<<B, NT>>>(logits, out, out + (size_t)B * NCOLS);
}